// round 1
// baseline (speedup 1.0000x reference)
#include <cuda_runtime.h>
#include <cuda_bf16.h>
#include <math.h>

// Problem constants
#define BB   8
#define SS   512
#define INP  128
#define DD   512
#define HH   8
#define DKK  64
#define DVV  64
#define DFFN 2048
#define LL   4
#define LOCAL_W 64
#define MM   (BB*SS)          // 4096 rows
#define HDK  (HH*DKK)         // 512

// -------- scratch (device globals; no allocation allowed) --------
__device__ float g_h  [MM*DD];
__device__ float g_q  [MM*HDK];
__device__ float g_k  [MM*HDK];
__device__ float g_v  [MM*HDK];
__device__ float g_ctx[MM*HDK];
__device__ float g_tmp[MM*DD];
__device__ float g_ff [MM*DFFN];

// ---------------- GEMM: C = A[M,K] @ W[K,N] + bias, optional GELU ----------------
#define BMT 64
#define BNT 64
#define BKT 16

__device__ __forceinline__ float gelu_tanh(float x) {
    float x3 = x * x * x;
    return 0.5f * x * (1.0f + tanhf(0.7978845608028654f * (x + 0.044715f * x3)));
}

__global__ void gemm_bias_kernel(const float* __restrict__ A,
                                 const float* __restrict__ W,
                                 const float* __restrict__ bias,
                                 float* __restrict__ C,
                                 int M, int K, int N, int do_gelu) {
    __shared__ float As[BKT][BMT + 4];
    __shared__ float Bs[BKT][BNT + 4];

    int tid = threadIdx.x;              // 256 threads
    int bm = blockIdx.y * BMT;
    int bn = blockIdx.x * BNT;
    int tx = tid & 15;                  // 0..15
    int ty = tid >> 4;                  // 0..15

    float acc[4][4];
#pragma unroll
    for (int i = 0; i < 4; i++)
#pragma unroll
        for (int j = 0; j < 4; j++) acc[i][j] = 0.f;

    for (int k0 = 0; k0 < K; k0 += BKT) {
#pragma unroll
        for (int i = 0; i < 4; i++) {
            int idx = tid + i * 256;          // 0..1023
            int m = idx >> 4;                 // 0..63
            int kk = idx & 15;                // 0..15
            As[kk][m] = A[(size_t)(bm + m) * K + k0 + kk];
        }
#pragma unroll
        for (int i = 0; i < 4; i++) {
            int idx = tid + i * 256;
            int kk = idx >> 6;                // 0..15
            int n = idx & 63;                 // 0..63
            Bs[kk][n] = W[(size_t)(k0 + kk) * N + bn + n];
        }
        __syncthreads();

#pragma unroll
        for (int kk = 0; kk < BKT; kk++) {
            float a[4], bv[4];
#pragma unroll
            for (int i = 0; i < 4; i++) a[i] = As[kk][ty * 4 + i];
#pragma unroll
            for (int j = 0; j < 4; j++) bv[j] = Bs[kk][tx * 4 + j];
#pragma unroll
            for (int i = 0; i < 4; i++)
#pragma unroll
                for (int j = 0; j < 4; j++) acc[i][j] += a[i] * bv[j];
        }
        __syncthreads();
    }

#pragma unroll
    for (int i = 0; i < 4; i++) {
        int m = bm + ty * 4 + i;
#pragma unroll
        for (int j = 0; j < 4; j++) {
            int n = bn + tx * 4 + j;
            float v = acc[i][j] + bias[n];
            if (do_gelu) v = gelu_tanh(v);
            C[(size_t)m * N + n] = v;
        }
    }
}

// ---------------- Sin/cos positional encoding add ----------------
__global__ void add_pe_kernel(float* __restrict__ h) {
    int i = blockIdx.x * blockDim.x + threadIdx.x;
    if (i >= MM * DD) return;
    int d = i & (DD - 1);
    int s = (i / DD) & (SS - 1);
    int even = d & ~1;
    // div = exp(-even * ln(10000)/D)
    float div = expf(-(float)even * (9.210340371976184f / (float)DD));
    float ang = (float)s * div;
    h[i] += (d & 1) ? cosf(ang) : sinf(ang);
}

// ---------------- h = LayerNorm(h + y) * g + b (in-place on h) ----------------
__global__ void add_ln_kernel(float* __restrict__ h, const float* __restrict__ y,
                              const float* __restrict__ g, const float* __restrict__ b) {
    int row = blockIdx.x;
    int t = threadIdx.x;                 // 256
    float* hr = h + (size_t)row * DD;
    const float* yr = y + (size_t)row * DD;
    float v0 = hr[t] + yr[t];
    float v1 = hr[t + 256] + yr[t + 256];

    __shared__ float red[256];
    red[t] = v0 + v1;
    __syncthreads();
    for (int s = 128; s > 0; s >>= 1) {
        if (t < s) red[t] += red[t + s];
        __syncthreads();
    }
    float mean = red[0] * (1.0f / DD);
    __syncthreads();

    float d0 = v0 - mean, d1 = v1 - mean;
    red[t] = d0 * d0 + d1 * d1;
    __syncthreads();
    for (int s = 128; s > 0; s >>= 1) {
        if (t < s) red[t] += red[t + s];
        __syncthreads();
    }
    float inv = rsqrtf(red[0] * (1.0f / DD) + 1e-5f);

    hr[t]       = d0 * inv * g[t]       + b[t];
    hr[t + 256] = d1 * inv * g[t + 256] + b[t + 256];
}

// ---------------- Band attention ----------------
// grid: (S, B*H), 128 threads. Computes ctx for one (b,h,q) row.
// If attn_base != nullptr, also writes the full S-wide softmax row
// (zeros off-band) at [b, layer, h, q, :].
__global__ void attn_kernel(const float* __restrict__ Q, const float* __restrict__ K,
                            const float* __restrict__ V, float* __restrict__ ctx,
                            float* __restrict__ attn_base, int layer) {
    int qpos = blockIdx.x;
    int bh = blockIdx.y;
    int b = bh >> 3;
    int hh = bh & 7;
    int t = threadIdx.x;

    int kv0 = max(0, qpos - LOCAL_W);
    int kv1 = min(SS - 1, qpos + LOCAL_W);
    int nk = kv1 - kv0 + 1;

    __shared__ float qs[DKK];
    __shared__ float p[132];
    __shared__ float red[128];

    size_t rowbase = ((size_t)b * SS + qpos) * HDK + hh * DKK;
    if (t < DKK) qs[t] = Q[rowbase + t];
    __syncthreads();

    float lmax = -1e30f;
    for (int ko = t; ko < nk; ko += 128) {
        const float* kr = K + (((size_t)b * SS + kv0 + ko) * HDK + hh * DKK);
        float acc = 0.f;
#pragma unroll
        for (int d = 0; d < DKK; d++) acc += qs[d] * kr[d];
        acc *= 0.125f;                 // 1/sqrt(64)
        p[ko] = acc;
        lmax = fmaxf(lmax, acc);
    }
    red[t] = lmax;
    __syncthreads();
    for (int s = 64; s > 0; s >>= 1) {
        if (t < s) red[t] = fmaxf(red[t], red[t + s]);
        __syncthreads();
    }
    float m = red[0];
    __syncthreads();

    float lsum = 0.f;
    for (int ko = t; ko < nk; ko += 128) {
        float e = expf(p[ko] - m);
        p[ko] = e;
        lsum += e;
    }
    red[t] = lsum;
    __syncthreads();
    for (int s = 64; s > 0; s >>= 1) {
        if (t < s) red[t] += red[t + s];
        __syncthreads();
    }
    float inv = 1.0f / red[0];
    __syncthreads();

    for (int ko = t; ko < nk; ko += 128) p[ko] *= inv;
    __syncthreads();

    if (t < DVV) {
        float acc = 0.f;
        for (int kk = 0; kk < nk; kk++)
            acc += p[kk] * V[(((size_t)b * SS + kv0 + kk) * HDK + hh * DVV) + t];
        ctx[rowbase + t] = acc;
    }

    if (attn_base) {
        size_t abase = ((((size_t)b * LL + layer) * HH + hh) * SS + qpos) * (size_t)SS;
        for (int kpos = t; kpos < SS; kpos += 128) {
            float val = (kpos >= kv0 && kpos <= kv1) ? p[kpos - kv0] : 0.f;
            attn_base[abase + kpos] = val;
        }
    }
}

// ---------------- Host orchestration ----------------
extern "C" void kernel_launch(void* const* d_in, const int* in_sizes, int n_in,
                              void* d_out, int out_size) {
    const float* x     = (const float*)d_in[0];
    const float* We    = (const float*)d_in[1];
    const float* be    = (const float*)d_in[2];
    const float* Wq    = (const float*)d_in[3];
    const float* bq    = (const float*)d_in[4];
    const float* Wk    = (const float*)d_in[5];
    const float* bk    = (const float*)d_in[6];
    const float* Wv    = (const float*)d_in[7];
    const float* bv    = (const float*)d_in[8];
    const float* Wo    = (const float*)d_in[9];
    const float* bo    = (const float*)d_in[10];
    const float* ln1_g = (const float*)d_in[11];
    const float* ln1_b = (const float*)d_in[12];
    const float* W1    = (const float*)d_in[13];
    const float* b1    = (const float*)d_in[14];
    const float* W2    = (const float*)d_in[15];
    const float* b2    = (const float*)d_in[16];
    const float* ln2_g = (const float*)d_in[17];
    const float* ln2_b = (const float*)d_in[18];

    float* out = (float*)d_out;

    float *h, *q, *k, *v, *ctx, *tmp, *ff;
    cudaGetSymbolAddress((void**)&h,   g_h);
    cudaGetSymbolAddress((void**)&q,   g_q);
    cudaGetSymbolAddress((void**)&k,   g_k);
    cudaGetSymbolAddress((void**)&v,   g_v);
    cudaGetSymbolAddress((void**)&ctx, g_ctx);
    cudaGetSymbolAddress((void**)&tmp, g_tmp);
    cudaGetSymbolAddress((void**)&ff,  g_ff);

    dim3 gThr(256);

    // embed + positional encoding
    gemm_bias_kernel<<<dim3(DD / BNT, MM / BMT), gThr>>>(x, We, be, h, MM, INP, DD, 0);
    add_pe_kernel<<<(MM * DD + 255) / 256, 256>>>(h);

    float* attn_out_base = out + (size_t)MM * DD;

    for (int l = 0; l < LL; l++) {
        const float* Wq_l = Wq + (size_t)l * DD * HDK;
        const float* bq_l = bq + (size_t)l * HDK;
        const float* Wk_l = Wk + (size_t)l * DD * HDK;
        const float* bk_l = bk + (size_t)l * HDK;
        const float* Wv_l = Wv + (size_t)l * DD * HDK;
        const float* bv_l = bv + (size_t)l * HDK;
        const float* Wo_l = Wo + (size_t)l * HDK * DD;
        const float* bo_l = bo + (size_t)l * DD;

        for (int pass = 0; pass < 2; pass++) {
            gemm_bias_kernel<<<dim3(HDK / BNT, MM / BMT), gThr>>>(h, Wq_l, bq_l, q, MM, DD, HDK, 0);
            gemm_bias_kernel<<<dim3(HDK / BNT, MM / BMT), gThr>>>(h, Wk_l, bk_l, k, MM, DD, HDK, 0);
            gemm_bias_kernel<<<dim3(HDK / BNT, MM / BMT), gThr>>>(h, Wv_l, bv_l, v, MM, DD, HDK, 0);

            attn_kernel<<<dim3(SS, BB * HH), 128>>>(q, k, v, ctx,
                                                    pass ? attn_out_base : nullptr, l);

            gemm_bias_kernel<<<dim3(DD / BNT, MM / BMT), gThr>>>(ctx, Wo_l, bo_l, tmp, MM, HDK, DD, 0);
            add_ln_kernel<<<MM, 256>>>(h, tmp, ln1_g + (size_t)l * DD, ln1_b + (size_t)l * DD);
        }

        const float* W1_l = W1 + (size_t)l * DD * DFFN;
        const float* b1_l = b1 + (size_t)l * DFFN;
        const float* W2_l = W2 + (size_t)l * DFFN * DD;
        const float* b2_l = b2 + (size_t)l * DD;

        gemm_bias_kernel<<<dim3(DFFN / BNT, MM / BMT), gThr>>>(h, W1_l, b1_l, ff, MM, DD, DFFN, 1);
        gemm_bias_kernel<<<dim3(DD / BNT, MM / BMT), gThr>>>(ff, W2_l, b2_l, tmp, MM, DFFN, DD, 0);
        add_ln_kernel<<<MM, 256>>>(h, tmp, ln2_g + (size_t)l * DD, ln2_b + (size_t)l * DD);
    }

    // h -> first B*S*D elements of output
    cudaMemcpyAsync(out, h, (size_t)MM * DD * sizeof(float), cudaMemcpyDeviceToDevice);
}

// round 3
// speedup vs baseline: 2.7347x; 2.7347x over previous
#include <cuda_runtime.h>
#include <math.h>

// Problem constants
#define BB   8
#define SS   512
#define INP  128
#define DD   512
#define HH   8
#define DKK  64
#define DVV  64
#define DFFN 2048
#define LL   4
#define MM   (BB*SS)          // 4096 rows
#define HDK  (HH*DKK)         // 512

// -------- scratch (device globals; no allocation allowed) --------
__device__ float g_h  [MM*DD];
__device__ float g_q  [MM*HDK];
__device__ float g_k  [MM*HDK];
__device__ float g_v  [MM*HDK];
__device__ float g_ctx[MM*HDK];
__device__ float g_tmp[MM*DD];
__device__ float g_ff [MM*DFFN];

__device__ __forceinline__ float gelu_tanh(float x) {
    float x3 = x * x * x;
    return 0.5f * x * (1.0f + tanhf(0.7978845608028654f * (x + 0.044715f * x3)));
}

// ================= SGEMM core: 128x128 block tile, BK=8, 256 thr, 8x8 micro =================
// As[8][132] (k-major, m minor), Bs[8][128]
__device__ __forceinline__ void gemm_core(const float* __restrict__ A,
                                          const float* __restrict__ W,
                                          const float* __restrict__ bias,
                                          float* __restrict__ C,
                                          int K, int N, int do_gelu,
                                          float (*As)[132], float (*Bs)[128],
                                          int bm, int bn) {
    int tid = threadIdx.x;
    int arow = tid >> 1, ac4 = (tid & 1) * 4;
    int brow = tid >> 5, bc4 = (tid & 31) * 4;
    const float* Aptr = A + (size_t)(bm + arow) * K + ac4;
    const float* Wptr = W + (size_t)brow * N + bn + bc4;
    int tx = tid & 15, ty = tid >> 4;

    float acc[8][8];
#pragma unroll
    for (int i = 0; i < 8; i++)
#pragma unroll
        for (int j = 0; j < 8; j++) acc[i][j] = 0.f;

    float4 ra = *(const float4*)Aptr;
    float4 rb = *(const float4*)Wptr;

    for (int k0 = 0; k0 < K; k0 += 8) {
        __syncthreads();
        As[ac4 + 0][arow] = ra.x;
        As[ac4 + 1][arow] = ra.y;
        As[ac4 + 2][arow] = ra.z;
        As[ac4 + 3][arow] = ra.w;
        *(float4*)&Bs[brow][bc4] = rb;
        __syncthreads();
        if (k0 + 8 < K) {
            ra = *(const float4*)(Aptr + k0 + 8);
            rb = *(const float4*)(Wptr + (size_t)(k0 + 8) * N);
        }
#pragma unroll
        for (int kk = 0; kk < 8; kk++) {
            float a[8], b[8];
            *(float4*)&a[0] = *(const float4*)&As[kk][ty * 8];
            *(float4*)&a[4] = *(const float4*)&As[kk][ty * 8 + 4];
            *(float4*)&b[0] = *(const float4*)&Bs[kk][tx * 8];
            *(float4*)&b[4] = *(const float4*)&Bs[kk][tx * 8 + 4];
#pragma unroll
            for (int i = 0; i < 8; i++)
#pragma unroll
                for (int j = 0; j < 8; j++) acc[i][j] += a[i] * b[j];
        }
    }

    // epilogue
    float bv[8];
#pragma unroll
    for (int j = 0; j < 8; j++) bv[j] = bias[bn + tx * 8 + j];
#pragma unroll
    for (int i = 0; i < 8; i++) {
        int row = bm + ty * 8 + i;
        float v[8];
#pragma unroll
        for (int j = 0; j < 8; j++) {
            float t = acc[i][j] + bv[j];
            v[j] = do_gelu ? gelu_tanh(t) : t;
        }
        float* cp = C + (size_t)row * N + bn + tx * 8;
        *(float4*)&cp[0] = *(float4*)&v[0];
        *(float4*)&cp[4] = *(float4*)&v[4];
    }
}

__global__ void __launch_bounds__(256) sgemm_kernel(const float* __restrict__ A,
                                                    const float* __restrict__ W,
                                                    const float* __restrict__ bias,
                                                    float* __restrict__ C,
                                                    int K, int N, int do_gelu) {
    __shared__ float As[8][132];
    __shared__ float Bs[8][128];
    gemm_core(A, W, bias, C, K, N, do_gelu, As, Bs,
              blockIdx.y * 128, blockIdx.x * 128);
}

// Fused QKV: grid.z in {0,1,2} selects (W,b,C) triple. N = HDK = 512, K = DD.
__global__ void __launch_bounds__(256) qkv_gemm_kernel(const float* __restrict__ A,
                                                       const float* __restrict__ Wq,
                                                       const float* __restrict__ Wk,
                                                       const float* __restrict__ Wv,
                                                       const float* __restrict__ bq,
                                                       const float* __restrict__ bk,
                                                       const float* __restrict__ bv,
                                                       float* __restrict__ q,
                                                       float* __restrict__ k,
                                                       float* __restrict__ v) {
    __shared__ float As[8][132];
    __shared__ float Bs[8][128];
    int z = blockIdx.z;
    const float* W = (z == 0) ? Wq : (z == 1) ? Wk : Wv;
    const float* b = (z == 0) ? bq : (z == 1) ? bk : bv;
    float* C = (z == 0) ? q : (z == 1) ? k : v;
    gemm_core(A, W, b, C, DD, HDK, 0, As, Bs, blockIdx.y * 128, blockIdx.x * 128);
}

// ---------------- Sin/cos positional encoding add ----------------
__global__ void add_pe_kernel(float* __restrict__ h) {
    int i = blockIdx.x * blockDim.x + threadIdx.x;
    if (i >= MM * DD) return;
    int d = i & (DD - 1);
    int s = (i / DD) & (SS - 1);
    int even = d & ~1;
    float div = expf(-(float)even * (9.210340371976184f / (float)DD));
    float ang = (float)s * div;
    h[i] += (d & 1) ? cosf(ang) : sinf(ang);
}

// ---------------- h = LayerNorm(h + y) * g + b (in-place on h) ----------------
__global__ void add_ln_kernel(float* __restrict__ h, const float* __restrict__ y,
                              const float* __restrict__ g, const float* __restrict__ b) {
    int row = blockIdx.x;
    int t = threadIdx.x;                 // 256
    float* hr = h + (size_t)row * DD;
    const float* yr = y + (size_t)row * DD;
    float v0 = hr[t] + yr[t];
    float v1 = hr[t + 256] + yr[t + 256];

    __shared__ float red[256];
    red[t] = v0 + v1;
    __syncthreads();
    for (int s = 128; s > 0; s >>= 1) {
        if (t < s) red[t] += red[t + s];
        __syncthreads();
    }
    float mean = red[0] * (1.0f / DD);
    __syncthreads();

    float d0 = v0 - mean, d1 = v1 - mean;
    red[t] = d0 * d0 + d1 * d1;
    __syncthreads();
    for (int s = 128; s > 0; s >>= 1) {
        if (t < s) red[t] += red[t + s];
        __syncthreads();
    }
    float inv = rsqrtf(red[0] * (1.0f / DD) + 1e-5f);

    hr[t]       = d0 * inv * g[t]       + b[t];
    hr[t + 256] = d1 * inv * g[t + 256] + b[t + 256];
}

// ================= Tiled band attention =================
// Block = (b, h, 32-q tile). 256 threads. Dynamic smem:
//   region0: KT [64][164] (d-major, c minor, float4-aligned) -> later reused as Vs [c][68]
//   region1: Qs [32][65]
//   region2: P  [32][160]
#define QT 32
#define BWMAX 160
#define KT_STRIDE 164
#define VS_STRIDE 68
#define OFF_QS  10880
#define OFF_P   (10880 + 2080)
#define ATTN_SMEM ((OFF_P + QT * BWMAX) * 4)

__global__ void __launch_bounds__(256) attn_tiled_kernel(const float* __restrict__ Q,
                                                         const float* __restrict__ K,
                                                         const float* __restrict__ V,
                                                         float* __restrict__ ctx,
                                                         float* __restrict__ attn_base,
                                                         int layer) {
    extern __shared__ float sm[];
    float* KT = sm;             // [64][KT_STRIDE]
    float* Qs = sm + OFF_QS;    // [32][65]
    float* P  = sm + OFF_P;     // [32][BWMAX]

    int tid = threadIdx.x;
    int q0 = blockIdx.x * QT;
    int bh = blockIdx.y;
    int b = bh >> 3;
    int h = bh & 7;
    int kv0 = max(0, q0 - 64);
    int kv1 = min(SS - 1, q0 + QT - 1 + 64);
    int w = kv1 - kv0 + 1;

    // load Q tile
    for (int idx = tid; idx < QT * 64; idx += 256) {
        int r = idx >> 6, d = idx & 63;
        Qs[r * 65 + d] = Q[((size_t)(b * SS + q0 + r)) * HDK + h * 64 + d];
    }
    // load K tile transposed
    for (int idx = tid; idx < w * 64; idx += 256) {
        int c = idx >> 6, d = idx & 63;
        KT[d * KT_STRIDE + c] = K[((size_t)(b * SS + kv0 + c)) * HDK + h * 64 + d];
    }
    __syncthreads();

    // scores: 4x4 micro-tiles
    for (int t = tid; t < 8 * 40; t += 256) {
        int r0 = (t / 40) * 4;
        int c0 = (t % 40) * 4;
        if (c0 >= w) continue;
        float acc[4][4];
#pragma unroll
        for (int i = 0; i < 4; i++)
#pragma unroll
            for (int j = 0; j < 4; j++) acc[i][j] = 0.f;
#pragma unroll 16
        for (int d = 0; d < 64; d++) {
            float4 kv = *(const float4*)&KT[d * KT_STRIDE + c0];
            float qv[4];
#pragma unroll
            for (int i = 0; i < 4; i++) qv[i] = Qs[(r0 + i) * 65 + d];
#pragma unroll
            for (int i = 0; i < 4; i++) {
                acc[i][0] += qv[i] * kv.x;
                acc[i][1] += qv[i] * kv.y;
                acc[i][2] += qv[i] * kv.z;
                acc[i][3] += qv[i] * kv.w;
            }
        }
#pragma unroll
        for (int i = 0; i < 4; i++)
#pragma unroll
            for (int j = 0; j < 4; j++) {
                int c = c0 + j;
                if (c < w) {
                    int diff = (q0 + r0 + i) - (kv0 + c);
                    if (diff < 0) diff = -diff;
                    P[(r0 + i) * BWMAX + c] = (diff <= 64) ? acc[i][j] * 0.125f : -1e30f;
                }
            }
    }
    __syncthreads();

    // softmax: one warp per row, 4 rows each
    int wi = tid >> 5, lane = tid & 31;
    for (int r = wi; r < QT; r += 8) {
        float m = -1e30f;
        for (int c = lane; c < w; c += 32) m = fmaxf(m, P[r * BWMAX + c]);
#pragma unroll
        for (int o = 16; o > 0; o >>= 1) m = fmaxf(m, __shfl_xor_sync(0xffffffffu, m, o));
        float s = 0.f;
        for (int c = lane; c < w; c += 32) {
            float e = expf(P[r * BWMAX + c] - m);
            P[r * BWMAX + c] = e;
            s += e;
        }
#pragma unroll
        for (int o = 16; o > 0; o >>= 1) s += __shfl_xor_sync(0xffffffffu, s, o);
        float inv = 1.0f / s;
        for (int c = lane; c < w; c += 32) P[r * BWMAX + c] *= inv;
    }
    __syncthreads();

    // load V into the KT region (layout [c][VS_STRIDE])
    float* Vs = sm;
    for (int idx = tid; idx < w * 64; idx += 256) {
        int c = idx >> 6, d = idx & 63;
        Vs[c * VS_STRIDE + d] = V[((size_t)(b * SS + kv0 + c)) * HDK + h * 64 + d];
    }
    __syncthreads();

    // PV: each thread 2 rows x 4 cols
    {
        int r0 = (tid >> 4) * 2;
        int d0 = (tid & 15) * 4;
        float4 a0 = {0.f, 0.f, 0.f, 0.f};
        float4 a1 = {0.f, 0.f, 0.f, 0.f};
        for (int c = 0; c < w; c++) {
            float p0 = P[r0 * BWMAX + c];
            float p1 = P[(r0 + 1) * BWMAX + c];
            float4 v = *(const float4*)&Vs[c * VS_STRIDE + d0];
            a0.x += p0 * v.x; a0.y += p0 * v.y; a0.z += p0 * v.z; a0.w += p0 * v.w;
            a1.x += p1 * v.x; a1.y += p1 * v.y; a1.z += p1 * v.z; a1.w += p1 * v.w;
        }
        size_t base0 = ((size_t)(b * SS + q0 + r0)) * HDK + h * 64 + d0;
        *(float4*)&ctx[base0] = a0;
        *(float4*)&ctx[base0 + HDK] = a1;
    }

    // write full S-wide attention rows (pass 2 only)
    if (attn_base) {
        size_t abase = ((((size_t)b * LL + layer) * HH + h) * SS + q0) * (size_t)SS;
        for (int idx = tid; idx < QT * SS; idx += 256) {
            int r = idx >> 9, kpos = idx & 511;
            float val = (kpos >= kv0 && kpos <= kv1) ? P[r * BWMAX + (kpos - kv0)] : 0.f;
            attn_base[abase + (size_t)r * SS + kpos] = val;
        }
    }
}

// ---------------- Host orchestration ----------------
extern "C" void kernel_launch(void* const* d_in, const int* in_sizes, int n_in,
                              void* d_out, int out_size) {
    const float* x     = (const float*)d_in[0];
    const float* We    = (const float*)d_in[1];
    const float* be    = (const float*)d_in[2];
    const float* Wq    = (const float*)d_in[3];
    const float* bq    = (const float*)d_in[4];
    const float* Wk    = (const float*)d_in[5];
    const float* bk    = (const float*)d_in[6];
    const float* Wv    = (const float*)d_in[7];
    const float* bv    = (const float*)d_in[8];
    const float* Wo    = (const float*)d_in[9];
    const float* bo    = (const float*)d_in[10];
    const float* ln1_g = (const float*)d_in[11];
    const float* ln1_b = (const float*)d_in[12];
    const float* W1    = (const float*)d_in[13];
    const float* b1    = (const float*)d_in[14];
    const float* W2    = (const float*)d_in[15];
    const float* b2    = (const float*)d_in[16];
    const float* ln2_g = (const float*)d_in[17];
    const float* ln2_b = (const float*)d_in[18];

    float* out = (float*)d_out;

    float *h, *q, *k, *v, *ctx, *tmp, *ff;
    cudaGetSymbolAddress((void**)&h,   g_h);
    cudaGetSymbolAddress((void**)&q,   g_q);
    cudaGetSymbolAddress((void**)&k,   g_k);
    cudaGetSymbolAddress((void**)&v,   g_v);
    cudaGetSymbolAddress((void**)&ctx, g_ctx);
    cudaGetSymbolAddress((void**)&tmp, g_tmp);
    cudaGetSymbolAddress((void**)&ff,  g_ff);

    cudaFuncSetAttribute(attn_tiled_kernel,
                         cudaFuncAttributeMaxDynamicSharedMemorySize, ATTN_SMEM);

    // embed + positional encoding
    sgemm_kernel<<<dim3(DD / 128, MM / 128), 256>>>(x, We, be, h, INP, DD, 0);
    add_pe_kernel<<<(MM * DD + 255) / 256, 256>>>(h);

    float* attn_out_base = out + (size_t)MM * DD;

    for (int l = 0; l < LL; l++) {
        const float* Wq_l = Wq + (size_t)l * DD * HDK;
        const float* bq_l = bq + (size_t)l * HDK;
        const float* Wk_l = Wk + (size_t)l * DD * HDK;
        const float* bk_l = bk + (size_t)l * HDK;
        const float* Wv_l = Wv + (size_t)l * DD * HDK;
        const float* bv_l = bv + (size_t)l * HDK;
        const float* Wo_l = Wo + (size_t)l * HDK * DD;
        const float* bo_l = bo + (size_t)l * DD;

        for (int pass = 0; pass < 2; pass++) {
            qkv_gemm_kernel<<<dim3(HDK / 128, MM / 128, 3), 256>>>(
                h, Wq_l, Wk_l, Wv_l, bq_l, bk_l, bv_l, q, k, v);

            attn_tiled_kernel<<<dim3(SS / QT, BB * HH), 256, ATTN_SMEM>>>(
                q, k, v, ctx, pass ? attn_out_base : nullptr, l);

            sgemm_kernel<<<dim3(DD / 128, MM / 128), 256>>>(ctx, Wo_l, bo_l, tmp, HDK, DD, 0);
            add_ln_kernel<<<MM, 256>>>(h, tmp, ln1_g + (size_t)l * DD, ln1_b + (size_t)l * DD);
        }

        const float* W1_l = W1 + (size_t)l * DD * DFFN;
        const float* b1_l = b1 + (size_t)l * DFFN;
        const float* W2_l = W2 + (size_t)l * DFFN * DD;
        const float* b2_l = b2 + (size_t)l * DD;

        sgemm_kernel<<<dim3(DFFN / 128, MM / 128), 256>>>(h, W1_l, b1_l, ff, DD, DFFN, 1);
        sgemm_kernel<<<dim3(DD / 128, MM / 128), 256>>>(ff, W2_l, b2_l, tmp, DFFN, DD, 0);
        add_ln_kernel<<<MM, 256>>>(h, tmp, ln2_g + (size_t)l * DD, ln2_b + (size_t)l * DD);
    }

    // h -> first B*S*D elements of output
    cudaMemcpyAsync(out, h, (size_t)MM * DD * sizeof(float), cudaMemcpyDeviceToDevice);
}

// round 6
// speedup vs baseline: 5.9246x; 2.1664x over previous
#include <cuda_runtime.h>
#include <cuda_bf16.h>
#include <math.h>
#include <stdint.h>

// Problem constants
#define BB   8
#define SS   512
#define INP  128
#define DD   512
#define HH   8
#define DKK  64
#define DVV  64
#define DFFN 2048
#define LL   4
#define MM   (BB*SS)          // 4096 rows
#define HDK  (HH*DKK)         // 512

// ================= scratch (device globals; no allocation allowed) =================
__device__ float g_h  [MM*DD];
__device__ float g_q  [MM*HDK];
__device__ float g_k  [MM*HDK];
__device__ float g_v  [MM*HDK];
__device__ float g_ctx[MM*HDK];
__device__ float g_tmp[MM*DD];
__device__ float g_ff [MM*DFFN];

// bf16 split scratch
#define W_TOTAL 12648448          // We^T + per-layer {Wq,Wk,Wv,Wo,W1,W2}^T
__device__ __align__(256) __nv_bfloat16 g_ahi[MM*DFFN];
__device__ __align__(256) __nv_bfloat16 g_alo[MM*DFFN];
__device__ __align__(256) __nv_bfloat16 g_whi[W_TOTAL];
__device__ __align__(256) __nv_bfloat16 g_wlo[W_TOTAL];

// weight layout offsets (elements)
#define OFF_WE   0
#define WE_SZ    (DD*INP)
#define LAYER_SZ (4*DD*DD + 2*DD*DFFN)
#define LOFF(l)  (WE_SZ + (size_t)(l)*LAYER_SZ)
#define OFF_WQ   0
#define OFF_WK   (DD*DD)
#define OFF_WV   (2*DD*DD)
#define OFF_WO   (3*DD*DD)
#define OFF_W1   (4*DD*DD)                   // [N=2048, K=512]
#define OFF_W2   (4*DD*DD + DD*DFFN)         // [N=512,  K=2048]

__device__ __forceinline__ float gelu_tanh(float x) {
    float x3 = x * x * x;
    return 0.5f * x * (1.0f + tanhf(0.7978845608028654f * (x + 0.044715f * x3)));
}

__device__ __forceinline__ uint32_t smem_u32(const void* p) {
    uint32_t a;
    asm("{ .reg .u64 t; cvta.to.shared.u64 t, %1; cvt.u32.u64 %0, t; }" : "=r"(a) : "l"(p));
    return a;
}

// ================= split kernels =================
__global__ void split_act_kernel(const float* __restrict__ A,
                                 __nv_bfloat16* __restrict__ hi,
                                 __nv_bfloat16* __restrict__ lo, int n4) {
    int i = blockIdx.x * blockDim.x + threadIdx.x;
    if (i >= n4) return;
    float4 a = ((const float4*)A)[i];
    __nv_bfloat16 h0 = __float2bfloat16(a.x), h1 = __float2bfloat16(a.y);
    __nv_bfloat16 h2 = __float2bfloat16(a.z), h3 = __float2bfloat16(a.w);
    __nv_bfloat162* hp = (__nv_bfloat162*)hi;
    __nv_bfloat162* lp = (__nv_bfloat162*)lo;
    hp[i * 2]     = __nv_bfloat162(h0, h1);
    hp[i * 2 + 1] = __nv_bfloat162(h2, h3);
    lp[i * 2]     = __nv_bfloat162(__float2bfloat16(a.x - __bfloat162float(h0)),
                                   __float2bfloat16(a.y - __bfloat162float(h1)));
    lp[i * 2 + 1] = __nv_bfloat162(__float2bfloat16(a.z - __bfloat162float(h2)),
                                   __float2bfloat16(a.w - __bfloat162float(h3)));
}

// W[K,N] fp32 -> W^T[N,K] bf16 hi/lo
__global__ void wsplit_kernel(const float* __restrict__ W,
                              __nv_bfloat16* __restrict__ hiT,
                              __nv_bfloat16* __restrict__ loT, int K, int N) {
    __shared__ float t[32][33];
    int k0 = blockIdx.y * 32, n0 = blockIdx.x * 32;
    int tx = threadIdx.x, ty = threadIdx.y;     // 32 x 8
#pragma unroll
    for (int i = 0; i < 32; i += 8)
        t[ty + i][tx] = W[(size_t)(k0 + ty + i) * N + n0 + tx];
    __syncthreads();
#pragma unroll
    for (int i = 0; i < 32; i += 8) {
        int n = n0 + ty + i, k = k0 + tx;
        float a = t[tx][ty + i];
        __nv_bfloat16 h = __float2bfloat16(a);
        hiT[(size_t)n * K + k] = h;
        loT[(size_t)n * K + k] = __float2bfloat16(a - __bfloat162float(h));
    }
}

// ================= mma.sync GEMM: C[M,N] = A[M,K] * B^T (B stored [N,K]) =================
// 128x128 tile per CTA, BK=32, double buffered cp.async, bf16x3 split.
#define TILE_BYTES  8192               // 128 rows x 64B (32 bf16)
#define STAGE_BYTES (4 * TILE_BYTES)   // Ahi, Alo, Bhi, Blo
#define GSMEM       (2 * STAGE_BYTES)  // 64 KB

#define CP16(s, g) asm volatile("cp.async.cg.shared.global [%0], [%1], 16;" :: "r"(s), "l"(g))
#define CP_COMMIT() asm volatile("cp.async.commit_group;" ::: "memory")

#define LDMX4(r, addr)                                                                   \
    asm volatile("ldmatrix.sync.aligned.m8n8.x4.shared.b16 {%0,%1,%2,%3}, [%4];"         \
        : "=r"((r)[0]), "=r"((r)[1]), "=r"((r)[2]), "=r"((r)[3]) : "r"(addr))

#define MMA16816(c, a, b0, b1)                                                           \
    asm volatile("mma.sync.aligned.m16n8k16.row.col.f32.bf16.bf16.f32 "                  \
        "{%0,%1,%2,%3}, {%4,%5,%6,%7}, {%8,%9}, {%0,%1,%2,%3};"                          \
        : "+f"((c)[0]), "+f"((c)[1]), "+f"((c)[2]), "+f"((c)[3])                         \
        : "r"((a)[0]), "r"((a)[1]), "r"((a)[2]), "r"((a)[3]), "r"(b0), "r"(b1))

// XOR swizzle: 16B chunk c of row r lands at chunk c ^ ((r>>1)&3)
__device__ __forceinline__ uint32_t sw_off(int r, int c) {
    return (uint32_t)(r * 64 + ((c ^ ((r >> 1) & 3)) << 4));
}

__device__ __forceinline__ void gemm_mma_core(
    const __nv_bfloat16* __restrict__ Ahi, const __nv_bfloat16* __restrict__ Alo,
    const __nv_bfloat16* __restrict__ Bhi, const __nv_bfloat16* __restrict__ Blo,
    const float* __restrict__ bias, float* __restrict__ C,
    int K, int N, int do_gelu, char* smem, int m0, int n0) {
    uint32_t sbase = smem_u32(smem);
    int tid = threadIdx.x, lane = tid & 31, wid = tid >> 5;
    int warp_m = wid >> 2, warp_n = wid & 3;

    const __nv_bfloat16* aH = Ahi + (size_t)m0 * K;
    const __nv_bfloat16* aL = Alo + (size_t)m0 * K;
    const __nv_bfloat16* bH = Bhi + (size_t)n0 * K;
    const __nv_bfloat16* bL = Blo + (size_t)n0 * K;

    float acc[4][4][4];
#pragma unroll
    for (int i = 0; i < 4; i++)
#pragma unroll
        for (int j = 0; j < 4; j++)
#pragma unroll
            for (int r = 0; r < 4; r++) acc[i][j][r] = 0.f;

    // ldmatrix lane->address components
    int rA = warp_m * 64 + ((lane >> 3) & 1) * 8 + (lane & 7);
    int cA = lane >> 4;                 // 0/1 k-chunk within k16
    int rB = warp_n * 32 + ((lane >> 4) & 1) * 8 + (lane & 7);
    int cB = (lane >> 3) & 1;

    // cp.async per-thread chunks (2 per tile)
    int idx0 = tid, idx1 = tid + 256;
    int r0c = idx0 >> 2, c0c = idx0 & 3;
    int r1c = idx1 >> 2, c1c = idx1 & 3;
    uint32_t so0 = sw_off(r0c, c0c), so1 = sw_off(r1c, c1c);

    int NC = K >> 5;                    // K/32

#define LOAD_STAGE(s, ko) do {                                                           \
    uint32_t sb = sbase + (s) * STAGE_BYTES;                                             \
    CP16(sb + so0,                  aH + (size_t)r0c * K + (ko) + c0c * 8);              \
    CP16(sb + so1,                  aH + (size_t)r1c * K + (ko) + c1c * 8);              \
    CP16(sb + TILE_BYTES + so0,     aL + (size_t)r0c * K + (ko) + c0c * 8);              \
    CP16(sb + TILE_BYTES + so1,     aL + (size_t)r1c * K + (ko) + c1c * 8);              \
    CP16(sb + 2*TILE_BYTES + so0,   bH + (size_t)r0c * K + (ko) + c0c * 8);              \
    CP16(sb + 2*TILE_BYTES + so1,   bH + (size_t)r1c * K + (ko) + c1c * 8);              \
    CP16(sb + 3*TILE_BYTES + so0,   bL + (size_t)r0c * K + (ko) + c0c * 8);              \
    CP16(sb + 3*TILE_BYTES + so1,   bL + (size_t)r1c * K + (ko) + c1c * 8);              \
    CP_COMMIT();                                                                          \
} while (0)

    LOAD_STAGE(0, 0);

    for (int kc = 0; kc < NC; kc++) {
        if (kc + 1 < NC) {
            LOAD_STAGE((kc + 1) & 1, (kc + 1) * 32);
            asm volatile("cp.async.wait_group 1;" ::: "memory");
        } else {
            asm volatile("cp.async.wait_group 0;" ::: "memory");
        }
        __syncthreads();

        uint32_t sAh = sbase + (kc & 1) * STAGE_BYTES;
        uint32_t sAl = sAh + TILE_BYTES;
        uint32_t sBh = sAh + 2 * TILE_BYTES;
        uint32_t sBl = sAh + 3 * TILE_BYTES;

#pragma unroll
        for (int ks = 0; ks < 2; ks++) {
            int cc = ks * 2;
            uint32_t ah[4][4], al[4][4];
#pragma unroll
            for (int mt = 0; mt < 4; mt++) {
                uint32_t off = sw_off(rA + mt * 16, cc + cA);
                LDMX4(ah[mt], sAh + off);
                LDMX4(al[mt], sAl + off);
            }
#pragma unroll
            for (int nt2 = 0; nt2 < 2; nt2++) {
                uint32_t off = sw_off(rB + nt2 * 16, cc + cB);
                uint32_t bh[4], bl[4];
                LDMX4(bh, sBh + off);
                LDMX4(bl, sBl + off);
#pragma unroll
                for (int mt = 0; mt < 4; mt++) {
#pragma unroll
                    for (int j = 0; j < 2; j++) {
                        float* a_ = acc[mt][nt2 * 2 + j];
                        MMA16816(a_, ah[mt], bh[2 * j], bh[2 * j + 1]);
                        MMA16816(a_, ah[mt], bl[2 * j], bl[2 * j + 1]);
                        MMA16816(a_, al[mt], bh[2 * j], bh[2 * j + 1]);
                    }
                }
            }
        }
        __syncthreads();
    }
#undef LOAD_STAGE

    // epilogue
    int mrow = m0 + warp_m * 64 + (lane >> 2);
    int ncol = n0 + warp_n * 32 + 2 * (lane & 3);
#pragma unroll
    for (int mt = 0; mt < 4; mt++) {
#pragma unroll
        for (int nt = 0; nt < 4; nt++) {
            int m = mrow + mt * 16;
            int n = ncol + nt * 8;
            float b0v = bias[n], b1v = bias[n + 1];
            float v0 = acc[mt][nt][0] + b0v;
            float v1 = acc[mt][nt][1] + b1v;
            float v2 = acc[mt][nt][2] + b0v;
            float v3 = acc[mt][nt][3] + b1v;
            if (do_gelu) {
                v0 = gelu_tanh(v0); v1 = gelu_tanh(v1);
                v2 = gelu_tanh(v2); v3 = gelu_tanh(v3);
            }
            float2 p0 = {v0, v1}, p1 = {v2, v3};
            *(float2*)&C[(size_t)m * N + n] = p0;
            *(float2*)&C[(size_t)(m + 8) * N + n] = p1;
        }
    }
}

__global__ void __launch_bounds__(256) gemm_mma_kernel(
    const __nv_bfloat16* __restrict__ Ahi, const __nv_bfloat16* __restrict__ Alo,
    const __nv_bfloat16* __restrict__ Bhi, const __nv_bfloat16* __restrict__ Blo,
    const float* __restrict__ bias, float* __restrict__ C,
    int K, int N, int do_gelu) {
    extern __shared__ char smem[];
    gemm_mma_core(Ahi, Alo, Bhi, Blo, bias, C, K, N, do_gelu, smem,
                  blockIdx.y * 128, blockIdx.x * 128);
}

// Fused QKV: grid.z selects (W,b,C). K=DD, N=HDK.
__global__ void __launch_bounds__(256) qkv_mma_kernel(
    const __nv_bfloat16* __restrict__ Ahi, const __nv_bfloat16* __restrict__ Alo,
    const __nv_bfloat16* __restrict__ Whi, const __nv_bfloat16* __restrict__ Wlo,
    const float* __restrict__ bq, const float* __restrict__ bk, const float* __restrict__ bv,
    float* __restrict__ q, float* __restrict__ k, float* __restrict__ v) {
    extern __shared__ char smem[];
    int z = blockIdx.z;
    const __nv_bfloat16* bh = Whi + (size_t)z * DD * DD;
    const __nv_bfloat16* bl = Wlo + (size_t)z * DD * DD;
    const float* bias = (z == 0) ? bq : (z == 1) ? bk : bv;
    float* C = (z == 0) ? q : (z == 1) ? k : v;
    gemm_mma_core(Ahi, Alo, bh, bl, bias, C, DD, HDK, 0, smem,
                  blockIdx.y * 128, blockIdx.x * 128);
}

// ---------------- Sin/cos positional encoding add ----------------
__global__ void add_pe_kernel(float* __restrict__ h) {
    int i = blockIdx.x * blockDim.x + threadIdx.x;
    if (i >= MM * DD) return;
    int d = i & (DD - 1);
    int s = (i / DD) & (SS - 1);
    int even = d & ~1;
    float div = expf(-(float)even * (9.210340371976184f / (float)DD));
    float ang = (float)s * div;
    h[i] += (d & 1) ? cosf(ang) : sinf(ang);
}

// ---------------- h = LayerNorm(h + y) * g + b (in-place on h) ----------------
__global__ void add_ln_kernel(float* __restrict__ h, const float* __restrict__ y,
                              const float* __restrict__ g, const float* __restrict__ b) {
    int row = blockIdx.x;
    int t = threadIdx.x;                 // 256
    float* hr = h + (size_t)row * DD;
    const float* yr = y + (size_t)row * DD;
    float v0 = hr[t] + yr[t];
    float v1 = hr[t + 256] + yr[t + 256];

    __shared__ float red[256];
    red[t] = v0 + v1;
    __syncthreads();
    for (int s = 128; s > 0; s >>= 1) {
        if (t < s) red[t] += red[t + s];
        __syncthreads();
    }
    float mean = red[0] * (1.0f / DD);
    __syncthreads();

    float d0 = v0 - mean, d1 = v1 - mean;
    red[t] = d0 * d0 + d1 * d1;
    __syncthreads();
    for (int s = 128; s > 0; s >>= 1) {
        if (t < s) red[t] += red[t + s];
        __syncthreads();
    }
    float inv = rsqrtf(red[0] * (1.0f / DD) + 1e-5f);

    hr[t]       = d0 * inv * g[t]       + b[t];
    hr[t + 256] = d1 * inv * g[t + 256] + b[t + 256];
}

// ================= Tiled band attention (unchanged) =================
#define QT 32
#define BWMAX 160
#define KT_STRIDE 164
#define VS_STRIDE 68
#define OFF_QS  10880
#define OFF_P   (10880 + 2080)
#define ATTN_SMEM ((OFF_P + QT * BWMAX) * 4)

__global__ void __launch_bounds__(256) attn_tiled_kernel(const float* __restrict__ Q,
                                                         const float* __restrict__ K,
                                                         const float* __restrict__ V,
                                                         float* __restrict__ ctx,
                                                         float* __restrict__ attn_base,
                                                         int layer) {
    extern __shared__ float smf[];
    float* KT = smf;
    float* Qs = smf + OFF_QS;
    float* P  = smf + OFF_P;

    int tid = threadIdx.x;
    int q0 = blockIdx.x * QT;
    int bh = blockIdx.y;
    int b = bh >> 3;
    int h = bh & 7;
    int kv0 = max(0, q0 - 64);
    int kv1 = min(SS - 1, q0 + QT - 1 + 64);
    int w = kv1 - kv0 + 1;

    for (int idx = tid; idx < QT * 64; idx += 256) {
        int r = idx >> 6, d = idx & 63;
        Qs[r * 65 + d] = Q[((size_t)(b * SS + q0 + r)) * HDK + h * 64 + d];
    }
    for (int idx = tid; idx < w * 64; idx += 256) {
        int c = idx >> 6, d = idx & 63;
        KT[d * KT_STRIDE + c] = K[((size_t)(b * SS + kv0 + c)) * HDK + h * 64 + d];
    }
    __syncthreads();

    for (int t = tid; t < 8 * 40; t += 256) {
        int r0 = (t / 40) * 4;
        int c0 = (t % 40) * 4;
        if (c0 >= w) continue;
        float acc[4][4];
#pragma unroll
        for (int i = 0; i < 4; i++)
#pragma unroll
            for (int j = 0; j < 4; j++) acc[i][j] = 0.f;
#pragma unroll 16
        for (int d = 0; d < 64; d++) {
            float4 kv = *(const float4*)&KT[d * KT_STRIDE + c0];
            float qv[4];
#pragma unroll
            for (int i = 0; i < 4; i++) qv[i] = Qs[(r0 + i) * 65 + d];
#pragma unroll
            for (int i = 0; i < 4; i++) {
                acc[i][0] += qv[i] * kv.x;
                acc[i][1] += qv[i] * kv.y;
                acc[i][2] += qv[i] * kv.z;
                acc[i][3] += qv[i] * kv.w;
            }
        }
#pragma unroll
        for (int i = 0; i < 4; i++)
#pragma unroll
            for (int j = 0; j < 4; j++) {
                int c = c0 + j;
                if (c < w) {
                    int diff = (q0 + r0 + i) - (kv0 + c);
                    if (diff < 0) diff = -diff;
                    P[(r0 + i) * BWMAX + c] = (diff <= 64) ? acc[i][j] * 0.125f : -1e30f;
                }
            }
    }
    __syncthreads();

    int wi = tid >> 5, lane = tid & 31;
    for (int r = wi; r < QT; r += 8) {
        float m = -1e30f;
        for (int c = lane; c < w; c += 32) m = fmaxf(m, P[r * BWMAX + c]);
#pragma unroll
        for (int o = 16; o > 0; o >>= 1) m = fmaxf(m, __shfl_xor_sync(0xffffffffu, m, o));
        float s = 0.f;
        for (int c = lane; c < w; c += 32) {
            float e = expf(P[r * BWMAX + c] - m);
            P[r * BWMAX + c] = e;
            s += e;
        }
#pragma unroll
        for (int o = 16; o > 0; o >>= 1) s += __shfl_xor_sync(0xffffffffu, s, o);
        float inv = 1.0f / s;
        for (int c = lane; c < w; c += 32) P[r * BWMAX + c] *= inv;
    }
    __syncthreads();

    float* Vs = smf;
    for (int idx = tid; idx < w * 64; idx += 256) {
        int c = idx >> 6, d = idx & 63;
        Vs[c * VS_STRIDE + d] = V[((size_t)(b * SS + kv0 + c)) * HDK + h * 64 + d];
    }
    __syncthreads();

    {
        int r0 = (tid >> 4) * 2;
        int d0 = (tid & 15) * 4;
        float4 a0 = {0.f, 0.f, 0.f, 0.f};
        float4 a1 = {0.f, 0.f, 0.f, 0.f};
        for (int c = 0; c < w; c++) {
            float p0 = P[r0 * BWMAX + c];
            float p1 = P[(r0 + 1) * BWMAX + c];
            float4 v = *(const float4*)&Vs[c * VS_STRIDE + d0];
            a0.x += p0 * v.x; a0.y += p0 * v.y; a0.z += p0 * v.z; a0.w += p0 * v.w;
            a1.x += p1 * v.x; a1.y += p1 * v.y; a1.z += p1 * v.z; a1.w += p1 * v.w;
        }
        size_t base0 = ((size_t)(b * SS + q0 + r0)) * HDK + h * 64 + d0;
        *(float4*)&ctx[base0] = a0;
        *(float4*)&ctx[base0 + HDK] = a1;
    }

    if (attn_base) {
        size_t abase = ((((size_t)b * LL + layer) * HH + h) * SS + q0) * (size_t)SS;
        for (int idx = tid; idx < QT * SS; idx += 256) {
            int r = idx >> 9, kpos = idx & 511;
            float val = (kpos >= kv0 && kpos <= kv1) ? P[r * BWMAX + (kpos - kv0)] : 0.f;
            attn_base[abase + (size_t)r * SS + kpos] = val;
        }
    }
}

// ================= Host orchestration =================
static inline void launch_split(const float* A, __nv_bfloat16* hi, __nv_bfloat16* lo, int n) {
    int n4 = n / 4;
    split_act_kernel<<<(n4 + 255) / 256, 256>>>(A, hi, lo, n4);
}

extern "C" void kernel_launch(void* const* d_in, const int* in_sizes, int n_in,
                              void* d_out, int out_size) {
    const float* x     = (const float*)d_in[0];
    const float* We    = (const float*)d_in[1];
    const float* be    = (const float*)d_in[2];
    const float* Wq    = (const float*)d_in[3];
    const float* bq    = (const float*)d_in[4];
    const float* Wk    = (const float*)d_in[5];
    const float* bk    = (const float*)d_in[6];
    const float* Wv    = (const float*)d_in[7];
    const float* bv    = (const float*)d_in[8];
    const float* Wo    = (const float*)d_in[9];
    const float* bo    = (const float*)d_in[10];
    const float* ln1_g = (const float*)d_in[11];
    const float* ln1_b = (const float*)d_in[12];
    const float* W1    = (const float*)d_in[13];
    const float* b1    = (const float*)d_in[14];
    const float* W2    = (const float*)d_in[15];
    const float* b2    = (const float*)d_in[16];
    const float* ln2_g = (const float*)d_in[17];
    const float* ln2_b = (const float*)d_in[18];

    float* out = (float*)d_out;

    float *h, *q, *k, *v, *ctx, *tmp, *ff;
    __nv_bfloat16 *ahi, *alo, *whi, *wlo;
    cudaGetSymbolAddress((void**)&h,   g_h);
    cudaGetSymbolAddress((void**)&q,   g_q);
    cudaGetSymbolAddress((void**)&k,   g_k);
    cudaGetSymbolAddress((void**)&v,   g_v);
    cudaGetSymbolAddress((void**)&ctx, g_ctx);
    cudaGetSymbolAddress((void**)&tmp, g_tmp);
    cudaGetSymbolAddress((void**)&ff,  g_ff);
    cudaGetSymbolAddress((void**)&ahi, g_ahi);
    cudaGetSymbolAddress((void**)&alo, g_alo);
    cudaGetSymbolAddress((void**)&whi, g_whi);
    cudaGetSymbolAddress((void**)&wlo, g_wlo);

    cudaFuncSetAttribute(attn_tiled_kernel,
                         cudaFuncAttributeMaxDynamicSharedMemorySize, ATTN_SMEM);
    cudaFuncSetAttribute(gemm_mma_kernel,
                         cudaFuncAttributeMaxDynamicSharedMemorySize, GSMEM);
    cudaFuncSetAttribute(qkv_mma_kernel,
                         cudaFuncAttributeMaxDynamicSharedMemorySize, GSMEM);

    dim3 wthr(32, 8);

    // ---- split/transpose all weights ----
    wsplit_kernel<<<dim3(DD / 32, INP / 32), wthr>>>(We, whi + OFF_WE, wlo + OFF_WE, INP, DD);
    for (int l = 0; l < LL; l++) {
        size_t lb = LOFF(l);
        wsplit_kernel<<<dim3(HDK / 32, DD / 32), wthr>>>(Wq + (size_t)l * DD * HDK, whi + lb + OFF_WQ, wlo + lb + OFF_WQ, DD, HDK);
        wsplit_kernel<<<dim3(HDK / 32, DD / 32), wthr>>>(Wk + (size_t)l * DD * HDK, whi + lb + OFF_WK, wlo + lb + OFF_WK, DD, HDK);
        wsplit_kernel<<<dim3(HDK / 32, DD / 32), wthr>>>(Wv + (size_t)l * DD * HDK, whi + lb + OFF_WV, wlo + lb + OFF_WV, DD, HDK);
        wsplit_kernel<<<dim3(DD / 32, HDK / 32), wthr>>>(Wo + (size_t)l * HDK * DD, whi + lb + OFF_WO, wlo + lb + OFF_WO, HDK, DD);
        wsplit_kernel<<<dim3(DFFN / 32, DD / 32), wthr>>>(W1 + (size_t)l * DD * DFFN, whi + lb + OFF_W1, wlo + lb + OFF_W1, DD, DFFN);
        wsplit_kernel<<<dim3(DD / 32, DFFN / 32), wthr>>>(W2 + (size_t)l * DFFN * DD, whi + lb + OFF_W2, wlo + lb + OFF_W2, DFFN, DD);
    }

    // ---- embed + positional encoding ----
    launch_split(x, ahi, alo, MM * INP);
    gemm_mma_kernel<<<dim3(DD / 128, MM / 128), 256, GSMEM>>>(
        ahi, alo, whi + OFF_WE, wlo + OFF_WE, be, h, INP, DD, 0);
    add_pe_kernel<<<(MM * DD + 255) / 256, 256>>>(h);

    float* attn_out_base = out + (size_t)MM * DD;

    for (int l = 0; l < LL; l++) {
        size_t lb = LOFF(l);
        const float* bq_l = bq + (size_t)l * HDK;
        const float* bk_l = bk + (size_t)l * HDK;
        const float* bv_l = bv + (size_t)l * HDK;
        const float* bo_l = bo + (size_t)l * DD;

        for (int pass = 0; pass < 2; pass++) {
            launch_split(h, ahi, alo, MM * DD);
            qkv_mma_kernel<<<dim3(HDK / 128, MM / 128, 3), 256, GSMEM>>>(
                ahi, alo, whi + lb + OFF_WQ, wlo + lb + OFF_WQ,
                bq_l, bk_l, bv_l, q, k, v);

            attn_tiled_kernel<<<dim3(SS / QT, BB * HH), 256, ATTN_SMEM>>>(
                q, k, v, ctx, pass ? attn_out_base : nullptr, l);

            launch_split(ctx, ahi, alo, MM * HDK);
            gemm_mma_kernel<<<dim3(DD / 128, MM / 128), 256, GSMEM>>>(
                ahi, alo, whi + lb + OFF_WO, wlo + lb + OFF_WO, bo_l, tmp, HDK, DD, 0);
            add_ln_kernel<<<MM, 256>>>(h, tmp, ln1_g + (size_t)l * DD, ln1_b + (size_t)l * DD);
        }

        launch_split(h, ahi, alo, MM * DD);
        gemm_mma_kernel<<<dim3(DFFN / 128, MM / 128), 256, GSMEM>>>(
            ahi, alo, whi + lb + OFF_W1, wlo + lb + OFF_W1, b1 + (size_t)l * DFFN, ff, DD, DFFN, 1);
        launch_split(ff, ahi, alo, MM * DFFN);
        gemm_mma_kernel<<<dim3(DD / 128, MM / 128), 256, GSMEM>>>(
            ahi, alo, whi + lb + OFF_W2, wlo + lb + OFF_W2, b2 + (size_t)l * DD, tmp, DFFN, DD, 0);
        add_ln_kernel<<<MM, 256>>>(h, tmp, ln2_g + (size_t)l * DD, ln2_b + (size_t)l * DD);
    }

    cudaMemcpyAsync(out, h, (size_t)MM * DD * sizeof(float), cudaMemcpyDeviceToDevice);
}